// round 3
// baseline (speedup 1.0000x reference)
#include <cuda_runtime.h>
#include <cstdint>

#define DIMS   1000
#define NLEV   10
#define NPIX   784
#define NBATCH 256
#define NCLS   10
#define PW     25      // 784 pixels -> 25 x u32 words
#define PWP    28      // padded row stride (28*4 = 112B, 16B multiple)

// ---------------- device scratch (no allocations allowed) ----------------
__device__ uint32_t g_posb[1024 * PWP];   // packed position sign bits, d-major rows
__device__ int      g_tpos[1024];         // Tpos[d] = sum_p position[p,d]
__device__ uint32_t g_sig[1024];          // 10-bit vt sign signature per dim
__device__ float    g_wt[1024 * 12];      // W transposed: g_wt[d*12 + c], padded

// ---------------- kernel A1: pack position sign bits --------------------
__global__ void pack_pos_kernel(const float* __restrict__ position) {
    int w = blockIdx.x;                         // word 0..24
    int d = blockIdx.y * 256 + threadIdx.x;     // dim 0..1023
    if (d >= DIMS) return;
    uint32_t bits = 0;
    int pbase = w * 32;
#pragma unroll
    for (int j = 0; j < 32; j++) {
        int p = pbase + j;
        if (p < NPIX) {
            float v = position[p * DIMS + d];
            bits |= (v > 0.0f ? 1u : 0u) << j;
        }
    }
    g_posb[d * PWP + w] = bits;
}

// ---------------- kernel A2: padding, Tpos, signatures, W^T -------------
__global__ void prep_kernel(const float* __restrict__ vt, const float* __restrict__ W) {
    int d = blockIdx.x * 256 + threadIdx.x;
    if (d >= 1024) return;
    g_posb[d * PWP + 25] = 0u;
    g_posb[d * PWP + 26] = 0u;
    g_posb[d * PWP + 27] = 0u;
    if (d >= DIMS) {               // pad rows fully zero
#pragma unroll
        for (int w = 0; w < PW; w++) g_posb[d * PWP + w] = 0u;
        g_tpos[d] = 0; g_sig[d] = 0;
        return;
    }
    int tot = 0;
#pragma unroll
    for (int w = 0; w < PW; w++) tot += __popc(g_posb[d * PWP + w]);
    g_tpos[d] = 2 * tot - NPIX;    // = sum_p position[p,d]
    uint32_t sig = 0;
#pragma unroll
    for (int l = 0; l < NLEV; l++)
        sig |= (vt[l * DIMS + d] > 0.0f ? 1u : 0u) << l;
    g_sig[d] = sig;
#pragma unroll
    for (int c = 0; c < NCLS; c++) g_wt[d * 12 + c] = W[c * DIMS + d];
    g_wt[d * 12 + 10] = 0.0f;
    g_wt[d * 12 + 11] = 0.0f;
}

// ---------------- kernel B: masks + half-sig unions + popcount core -----
// 2 batches per CTA; all tables in STATIC shared memory (~17.8KB).
__global__ __launch_bounds__(256) void hdc_kernel(const float* __restrict__ x,
                                                  float* __restrict__ out) {
    // [batch][half: 0=lo,1=hi][32 sigs][PWP words]
    __shared__ __align__(16) uint32_t Mun[2][2][32][PWP];
    __shared__ int      Cun[2][2][32];
    __shared__ __align__(16) uint32_t mask[2][NLEV][PWP];
    __shared__ int      cnt[2][NLEV];
    __shared__ float    wred[2][8][NCLS];

    const int tid  = threadIdx.x;
    const int lane = tid & 31;
    const int warp = tid >> 5;

    // ---- init: zero masks (incl. padding words) ----
    for (int i = tid; i < 2 * NLEV * PWP; i += 256)
        ((uint32_t*)mask)[i] = 0u;
    __syncthreads();

    // ---- phase 1: per-batch level masks via ballot ----
#pragma unroll
    for (int bi = 0; bi < 2; bi++) {
        const float* xb = x + (blockIdx.x * 2 + bi) * NPIX;
        for (int base = 0; base < 1024; base += 256) {
            int p = base + tid;
            int lvl = -1;
            if (p < NPIX) {
                float xv = xb[p];
                int q = (int)rintf(xv * 9.0f);   // round-half-even == jnp.round
                q = q < 0 ? 0 : (q > 9 ? 9 : q);
                lvl = q;
            }
            int word = (base >> 5) + warp;
#pragma unroll
            for (int l = 0; l < NLEV; l++) {
                unsigned bm = __ballot_sync(0xffffffffu, lvl == l);
                if (lane == 0 && word < PW) mask[bi][l][word] = bm;
            }
        }
    }
    __syncthreads();

    if (tid < 2 * NLEV) {
        int bi = tid / NLEV, l = tid % NLEV;
        int c = 0;
#pragma unroll
        for (int w = 0; w < PW; w++) c += __popc(mask[bi][l][w]);
        cnt[bi][l] = c;
    }
    __syncthreads();

    // ---- phase 2: direct unions for each 5-bit half signature ----
    // 128 tasks: (batch, half, sig5); each unions <=5 disjoint level masks.
    if (tid < 128) {
        int bi   = tid >> 6;            // 0..1
        int half = (tid >> 5) & 1;      // 0..1
        int sg   = tid & 31;            // 0..31
        int lbase = half * 5;
        int c = 0;
#pragma unroll
        for (int l = 0; l < 5; l++)
            if (sg & (1 << l)) c += cnt[bi][lbase + l];
        Cun[bi][half][sg] = c;
        uint4* dst = (uint4*)&Mun[bi][half][sg][0];
#pragma unroll
        for (int q = 0; q < 7; q++) {
            uint4 r = make_uint4(0u, 0u, 0u, 0u);
#pragma unroll
            for (int l = 0; l < 5; l++) {
                if (sg & (1 << l)) {
                    uint4 m = ((const uint4*)&mask[bi][lbase + l][0])[q];
                    r.x |= m.x; r.y |= m.y; r.z |= m.z; r.w |= m.w;
                }
            }
            dst[q] = r;
        }
    }
    __syncthreads();

    // ---- phase 3: popcount core + classifier partials (both batches) ----
    float part[2][NCLS];
#pragma unroll
    for (int bi = 0; bi < 2; bi++)
#pragma unroll
        for (int c = 0; c < NCLS; c++) part[bi][c] = 0.0f;

    if (tid < 250) {
#pragma unroll
        for (int i = 0; i < 4; i++) {
            int d = i * 250 + tid;                 // d < 1000
            uint32_t sig = g_sig[d];
            int siglo = sig & 31, sighi = (sig >> 5) & 31;
            const uint4* pb4 = (const uint4*)&g_posb[d * PWP];
            int tpos = g_tpos[d];
            const float4* w4 = (const float4*)&g_wt[d * 12];
            float4 w0 = w4[0], w1 = w4[1], w2 = w4[2];
#pragma unroll
            for (int bi = 0; bi < 2; bi++) {
                const uint4* lo4 = (const uint4*)&Mun[bi][0][siglo][0];
                const uint4* hi4 = (const uint4*)&Mun[bi][1][sighi][0];
                int acc = 0;
#pragma unroll
                for (int q = 0; q < 7; q++) {
                    uint4 a = lo4[q], b = hi4[q], p = pb4[q];
                    acc += __popc(a.x & p.x) + __popc(a.y & p.y)
                         + __popc(a.z & p.z) + __popc(a.w & p.w);
                    acc += __popc(b.x & p.x) + __popc(b.y & p.y)
                         + __popc(b.z & p.z) + __popc(b.w & p.w);
                }
                int csum = Cun[bi][0][siglo] + Cun[bi][1][sighi];
                int s = 4 * acc - 2 * csum - tpos;
                float enc = (s > 0) ? 1.0f : -1.0f;
                part[bi][0] += enc * w0.x; part[bi][1] += enc * w0.y;
                part[bi][2] += enc * w0.z; part[bi][3] += enc * w0.w;
                part[bi][4] += enc * w1.x; part[bi][5] += enc * w1.y;
                part[bi][6] += enc * w1.z; part[bi][7] += enc * w1.w;
                part[bi][8] += enc * w2.x; part[bi][9] += enc * w2.y;
            }
        }
    }

    // ---- deterministic reduction: warp shuffle + fixed-order smem sum ----
#pragma unroll
    for (int bi = 0; bi < 2; bi++) {
#pragma unroll
        for (int c = 0; c < NCLS; c++) {
            float v = part[bi][c];
            v += __shfl_down_sync(0xffffffffu, v, 16);
            v += __shfl_down_sync(0xffffffffu, v, 8);
            v += __shfl_down_sync(0xffffffffu, v, 4);
            v += __shfl_down_sync(0xffffffffu, v, 2);
            v += __shfl_down_sync(0xffffffffu, v, 1);
            if (lane == 0) wred[bi][warp][c] = v;
        }
    }
    __syncthreads();

    if (tid < 2 * NCLS) {
        int bi = tid / NCLS, c = tid % NCLS;
        float s = 0.0f;
#pragma unroll
        for (int w = 0; w < 8; w++) s += wred[bi][w][c];
        out[(blockIdx.x * 2 + bi) * NCLS + c] = s;
    }
}

// ---------------- launch ----------------
extern "C" void kernel_launch(void* const* d_in, const int* in_sizes, int n_in,
                              void* d_out, int out_size) {
    const float* x        = (const float*)d_in[0];   // [256, 28, 28]
    const float* position = (const float*)d_in[1];   // [784, 1000]
    const float* vt       = (const float*)d_in[2];   // [10, 1000]
    const float* W        = (const float*)d_in[3];   // [10, 1000]
    float* out = (float*)d_out;                      // [256, 10]

    pack_pos_kernel<<<dim3(25, 4), 256>>>(position);
    prep_kernel<<<4, 256>>>(vt, W);
    hdc_kernel<<<128, 256>>>(x, out);
}